// round 6
// baseline (speedup 1.0000x reference)
#include <cuda_runtime.h>
#include <math.h>
#include <stdint.h>

// Problem constants
#define B_SZ   4
#define L_SZ   5
#define NIMG   20          // B*L
#define CH     64
#define IMH    256
#define IMW    128
#define HW     (IMH*IMW)   // 32768

// ---------------- scratch (static device globals; no allocation) ----------------
__device__ unsigned g_nbf[NIMG * 32 * HW];            // sampled input, bf16 pairs (n,cpair,h,w)
__device__ unsigned g_c1bf[NIMG * 16 * 128 * 64];     // conv1 out bf16 pairs
__device__ unsigned g_c2bf[NIMG * 32 * 64 * 32];      // conv2 out bf16 pairs
__device__ float    g_c3[NIMG * 64 * 32 * 16];        // conv3 out fp32
__device__ float    g_pool[NIMG * 64];
__device__ float    g_attn[B_SZ * L_SZ];

// ---------------- helpers ----------------
__device__ __forceinline__ unsigned pack_bf16(float lo, float hi) {
    unsigned u;
    asm("cvt.rn.bf16x2.f32 %0, %1, %2;" : "=r"(u) : "f"(hi), "f"(lo));
    return u;
}
__device__ __forceinline__ int pcmap(int p) { return ((p & 3) << 1) | (p >> 2); }

// ---------------- Kernel 1: affine grid + bilinear sample -> bf16 pairs ----------------
__global__ void sample_kernel(const float* __restrict__ x, const float* __restrict__ nam)
{
    const int n  = blockIdx.y;
    const int yy = blockIdx.x;
    const int xx = threadIdx.x;
    const int b  = n / L_SZ, l = n % L_SZ;

    const float* th = nam + (b * 25 + l) * 6;
    const float t00 = th[0], t01 = th[1], t02 = th[2];
    const float t10 = th[3], t11 = th[4], t12 = th[5];

    const float gxn = (xx + 0.5f) * (2.0f / IMW) - 1.0f;
    const float gyn = (yy + 0.5f) * (2.0f / IMH) - 1.0f;
    const float gx = t00 * gxn + t01 * gyn + t02;
    const float gy = t10 * gxn + t11 * gyn + t12;
    const float sx = ((gx + 1.0f) * IMW - 1.0f) * 0.5f;
    const float sy = ((gy + 1.0f) * IMH - 1.0f) * 0.5f;

    const float x0f = floorf(sx), y0f = floorf(sy);
    const float fx = sx - x0f, fy = sy - y0f;
    const int x0 = (int)x0f, y0 = (int)y0f;

    const int   xs[2] = { x0, x0 + 1 };
    const int   ys[2] = { y0, y0 + 1 };
    const float wx[2] = { 1.0f - fx, fx };
    const float wy[2] = { 1.0f - fy, fy };

    int   off[4];
    float wv[4];
    int k = 0;
    #pragma unroll
    for (int jy = 0; jy < 2; jy++)
        #pragma unroll
        for (int jx = 0; jx < 2; jx++, k++) {
            const int ix = xs[jx], iy = ys[jy];
            const bool v = (ix >= 0) && (ix < IMW) && (iy >= 0) && (iy < IMH);
            const int icx = min(max(ix, 0), IMW - 1);
            const int icy = min(max(iy, 0), IMH - 1);
            off[k] = icy * IMW + icx;
            wv[k]  = v ? wx[jx] * wy[jy] : 0.0f;
        }

    const float* img = x + (size_t)n * CH * HW;
    unsigned* dst = g_nbf + (size_t)n * 32 * HW + yy * IMW + xx;
    #pragma unroll 4
    for (int p = 0; p < 32; p++) {
        const float* i0 = img + (size_t)(2 * p) * HW;
        const float* i1 = i0 + HW;
        const float v0 = wv[0]*i0[off[0]] + wv[1]*i0[off[1]] + wv[2]*i0[off[2]] + wv[3]*i0[off[3]];
        const float v1 = wv[0]*i1[off[0]] + wv[1]*i1[off[1]] + wv[2]*i1[off[2]] + wv[3]*i1[off[3]];
        dst[(size_t)p * HW] = pack_bf16(v0, v1);
    }
}

// ---------------- bf16 tensor-core conv 4x4 s2 p1 + bias + relu ----------------
// m16n8k16: M=128 positions/CTA, N=COUTB, K = 16 cins per chunk (8 pairs).
// Input arrives as bf16 pairs (no cvt). A pitch 12 uints/position, B [tap][cout][8]
// — both conflict-free for LDS.64 fragment fetches. Register-pipelined staging.
template<int CIN, int COUT, int IH, int IW, int COUTB, bool OBF>
__global__ __launch_bounds__(256, 2)
void conv_bf16(const unsigned* __restrict__ in, const float* __restrict__ wgt,
               const float* __restrict__ bias, float* __restrict__ outf,
               unsigned* __restrict__ outu)
{
    constexpr int OH   = IH / 2, OW = IW / 2;
    constexpr int ROWS = 128 / OW;
    constexpr int INR  = 2 * ROWS + 2;
    constexpr int WP   = IW + 2;
    constexpr int AP   = 12;                 // uint pitch per input position
    constexpr int CP2  = CIN / 2;            // total cin pairs
    constexpr int NT   = COUTB / 8;
    constexpr int SPR  = OW / 16;
    constexpr int SINU = 8 * INR * WP;       // staged input uints per chunk
    constexpr int NI   = (SINU + 255) / 256;
    constexpr int NWU  = (16 * COUTB * 8) / 256;
    static_assert(ROWS * OW == 128 && 8 % SPR == 0, "tiling");

    extern __shared__ unsigned smu[];
    unsigned* s_win = smu;                   // [INR*WP][AP]
    unsigned* s_w   = smu + INR * WP * AP;   // [16][COUTB][8]

    const int n     = blockIdx.y;
    const int oy0   = blockIdx.x * ROWS;
    const int cbase = blockIdx.z * COUTB;
    const int t     = threadIdx.x;
    const int warp  = t >> 5;
    const int lane  = t & 31;

    const int row_local = warp / SPR;
    const int ox0       = (warp % SPR) * 16;
    const int qid       = lane >> 2;
    const int ci0       = lane & 3;

    float acc[NT][4];
    #pragma unroll
    for (int j = 0; j < NT; j++)
        #pragma unroll
        for (int p = 0; p < 4; p++) acc[j][p] = 0.0f;

    const unsigned* inN = in + (size_t)n * CP2 * IH * IW;
    const int y0 = 2 * oy0 - 1;

    unsigned rin[NI];
    unsigned rwu[NWU];

    auto LOAD = [&](int cb2) {               // cb2 = pair base
        #pragma unroll
        for (int i = 0; i < NI; i++) {
            const int idx = t + i * 256;
            unsigned v = 0u;
            if (idx < SINU) {
                const int p   = idx / (INR * WP);
                const int rem = idx % (INR * WP);
                const int rr  = rem / WP, col = rem % WP;
                const int iy = y0 + rr, ix = col - 1;
                if (iy >= 0 && iy < IH && (unsigned)ix < (unsigned)IW)
                    v = inN[(size_t)(cb2 + p) * IH * IW + (size_t)iy * IW + ix];
            }
            rin[i] = v;
        }
        #pragma unroll
        for (int i = 0; i < NWU; i++) {
            const int idx = t + i * 256;
            const int o = idx >> 7, rem = idx & 127;
            const int p = rem >> 4, tap = rem & 15;
            const float f0 = wgt[(size_t)(cbase + o) * CIN * 16 + (size_t)(2 * (cb2 + p)) * 16 + tap];
            const float f1 = wgt[(size_t)(cbase + o) * CIN * 16 + (size_t)(2 * (cb2 + p) + 1) * 16 + tap];
            rwu[i] = pack_bf16(f0, f1);
        }
    };
    auto STORE = [&]() {
        #pragma unroll
        for (int i = 0; i < NI; i++) {
            const int idx = t + i * 256;
            if (idx < SINU) {
                const int p   = idx / (INR * WP);
                const int rem = idx % (INR * WP);
                s_win[rem * AP + pcmap(p)] = rin[i];
            }
        }
        #pragma unroll
        for (int i = 0; i < NWU; i++) {
            const int idx = t + i * 256;
            const int o = idx >> 7, rem = idx & 127;
            const int p = rem >> 4, tap = rem & 15;
            s_w[(tap * COUTB + o) * 8 + pcmap(p)] = rwu[i];
        }
    };

    LOAD(0);
    STORE();
    __syncthreads();

    for (int cb2 = 0; cb2 < CP2; cb2 += 8) {
        const bool more = (cb2 + 8 < CP2);
        if (more) LOAD(cb2 + 8);

        #pragma unroll
        for (int ky = 0; ky < 4; ky++) {
            const unsigned* rowp = &s_win[((2 * row_local + ky) * WP + 2 * (ox0 + qid)) * AP + 2 * ci0];
            #pragma unroll
            for (int kx = 0; kx < 4; kx++) {
                const uint2 A0 = *(const uint2*)(rowp + kx * AP);          // {a0, a2}
                const uint2 A1 = *(const uint2*)(rowp + (kx + 16) * AP);   // {a1, a3}
                const int tap = ky * 4 + kx;
                #pragma unroll
                for (int j = 0; j < NT; j++) {
                    const uint2 Bv = *(const uint2*)&s_w[(tap * COUTB + j * 8 + qid) * 8 + 2 * ci0];
                    asm volatile(
                        "mma.sync.aligned.m16n8k16.row.col.f32.bf16.bf16.f32 "
                        "{%0,%1,%2,%3}, {%4,%5,%6,%7}, {%8,%9}, {%0,%1,%2,%3};"
                        : "+f"(acc[j][0]), "+f"(acc[j][1]), "+f"(acc[j][2]), "+f"(acc[j][3])
                        : "r"(A0.x), "r"(A1.x), "r"(A0.y), "r"(A1.y),
                          "r"(Bv.x), "r"(Bv.y));
                }
            }
        }
        __syncthreads();
        if (more) { STORE(); __syncthreads(); }
    }

    // epilogue: bias + relu
    const int oy = oy0 + row_local;
    const int ox = ox0 + qid;
    #pragma unroll
    for (int j = 0; j < NT; j++) {
        const int c0i = cbase + j * 8 + 2 * ci0;
        const float bv0 = bias[c0i], bv1 = bias[c0i + 1];
        const float v0 = fmaxf(acc[j][0] + bv0, 0.0f);
        const float v1 = fmaxf(acc[j][1] + bv1, 0.0f);
        const float v2 = fmaxf(acc[j][2] + bv0, 0.0f);
        const float v3 = fmaxf(acc[j][3] + bv1, 0.0f);
        if (OBF) {
            const int gp = (cbase >> 1) + j * 4 + ci0;
            unsigned* ob = outu + ((size_t)n * (COUT / 2) + gp) * OH * OW + (size_t)oy * OW;
            ob[ox]     = pack_bf16(v0, v1);
            ob[ox + 8] = pack_bf16(v2, v3);
        } else {
            float* o0 = outf + (((size_t)n * COUT + c0i) * OH + oy) * OW;
            float* o1 = outf + (((size_t)n * COUT + c0i + 1) * OH + oy) * OW;
            o0[ox]     = v0;
            o1[ox]     = v1;
            o0[ox + 8] = v2;
            o1[ox + 8] = v3;
        }
    }
}

// ---------------- mean pool: one warp per (n, c) reduction over 512 ----------------
__global__ void pool_kernel()
{
    const int gw   = (blockIdx.x * blockDim.x + threadIdx.x) >> 5;
    const int lane = threadIdx.x & 31;
    const float4* p = (const float4*)(g_c3 + (size_t)gw * 512);
    float s = 0.0f;
    #pragma unroll
    for (int i = lane; i < 128; i += 32) {
        const float4 v = p[i];
        s += (v.x + v.y) + (v.z + v.w);
    }
    #pragma unroll
    for (int o = 16; o; o >>= 1) s += __shfl_xor_sync(0xffffffffu, s, o);
    if (lane == 0) g_pool[gw] = s * (1.0f / 512.0f);
}

// ---------------- attention: MLPs + softmax ----------------
__global__ void attn_kernel(const float* __restrict__ kf1w, const float* __restrict__ kf1b,
                            const float* __restrict__ kf2w, const float* __restrict__ kf2b,
                            const float* __restrict__ kf3w, const float* __restrict__ kf3b,
                            const float* __restrict__ qf1w, const float* __restrict__ qf1b,
                            const float* __restrict__ qf2w, const float* __restrict__ qf2b,
                            const float* __restrict__ qf3w, const float* __restrict__ qf3b,
                            const float* __restrict__ aw,   const float* __restrict__ ab)
{
    const int b = blockIdx.x;
    const int t = threadIdx.x;

    __shared__ float pooled[L_SZ][64];
    __shared__ float h1[L_SZ][256];
    __shared__ float h2[L_SZ][128];
    __shared__ float keys[L_SZ][256];
    __shared__ float q1[256], q2[128], qv[32], qq[256];
    __shared__ float logit[L_SZ];

    for (int idx = t; idx < L_SZ * 64; idx += 256) {
        const int l = idx / 64, c = idx % 64;
        pooled[l][c] = g_pool[(b * L_SZ + l) * 64 + c];
    }
    __syncthreads();

    for (int idx = t; idx < L_SZ * 256; idx += 256) {
        const int l = idx / 256, o = idx % 256;
        float s = kf1b[o];
        for (int i = 0; i < 64; i++) s = fmaf(pooled[l][i], kf1w[o * 64 + i], s);
        h1[l][o] = fmaxf(s, 0.0f);
    }
    __syncthreads();
    for (int idx = t; idx < L_SZ * 128; idx += 256) {
        const int l = idx / 128, o = idx % 128;
        float s = kf2b[o];
        for (int i = 0; i < 256; i++) s = fmaf(h1[l][i], kf2w[o * 256 + i], s);
        h2[l][o] = fmaxf(s, 0.0f);
    }
    __syncthreads();
    for (int idx = t; idx < L_SZ * 256; idx += 256) {
        const int l = idx / 256, o = idx % 256;
        float s = kf3b[o];
        for (int i = 0; i < 128; i++) s = fmaf(h2[l][i], kf3w[o * 128 + i], s);
        keys[l][o] = s;
    }
    __syncthreads();

    {
        float s = qf1b[t];
        for (int i = 0; i < 64; i++) s = fmaf(pooled[0][i], qf1w[t * 64 + i], s);
        q1[t] = fmaxf(s, 0.0f);
    }
    __syncthreads();
    if (t < 128) {
        float s = qf2b[t];
        for (int i = 0; i < 256; i++) s = fmaf(q1[i], qf2w[t * 256 + i], s);
        q2[t] = fmaxf(s, 0.0f);
    }
    __syncthreads();
    if (t < 32) {
        float s = qf3b[t];
        for (int i = 0; i < 128; i++) s = fmaf(q2[i], qf3w[t * 128 + i], s);
        qv[t] = s;
    }
    __syncthreads();
    {
        float s = ab[t];
        for (int i = 0; i < 32; i++) s = fmaf(qv[i], aw[t * 32 + i], s);
        qq[t] = s;
    }
    __syncthreads();
    if (t < L_SZ) {
        float s = 0.0f;
        for (int i = 0; i < 256; i++) s = fmaf(keys[t][i], qq[i], s);
        logit[t] = s;
    }
    __syncthreads();
    if (t == 0) {
        float m = logit[0];
        for (int l = 1; l < L_SZ; l++) m = fmaxf(m, logit[l]);
        float e[L_SZ], ssum = 0.0f;
        for (int l = 0; l < L_SZ; l++) { e[l] = expf(logit[l] - m); ssum += e[l]; }
        const float inv = 1.0f / ssum;
        for (int l = 0; l < L_SZ; l++) g_attn[b * L_SZ + l] = e[l] * inv;
    }
}

// ---------------- fuse: bilinear resample from x + attention-weighted sum (fp32) ----------------
__global__ void fuse_kernel(float* __restrict__ out, const float* __restrict__ x,
                            const float* __restrict__ nam)
{
    const int b  = blockIdx.y;
    const int yy = blockIdx.x;
    const int xx = threadIdx.x;

    int   off[L_SZ][4];
    float wv[L_SZ][4];

    #pragma unroll
    for (int l = 0; l < L_SZ; l++) {
        const float* th = nam + (b * 25 + l) * 6;
        const float gxn = (xx + 0.5f) * (2.0f / IMW) - 1.0f;
        const float gyn = (yy + 0.5f) * (2.0f / IMH) - 1.0f;
        const float gx = th[0] * gxn + th[1] * gyn + th[2];
        const float gy = th[3] * gxn + th[4] * gyn + th[5];
        const float sx = ((gx + 1.0f) * IMW - 1.0f) * 0.5f;
        const float sy = ((gy + 1.0f) * IMH - 1.0f) * 0.5f;
        const float x0f = floorf(sx), y0f = floorf(sy);
        const float fx = sx - x0f, fy = sy - y0f;
        const int x0 = (int)x0f, y0 = (int)y0f;
        const float a = g_attn[b * L_SZ + l];

        const int   xs[2] = { x0, x0 + 1 };
        const int   ys[2] = { y0, y0 + 1 };
        const float wx[2] = { 1.0f - fx, fx };
        const float wy[2] = { 1.0f - fy, fy };
        int k = 0;
        #pragma unroll
        for (int jy = 0; jy < 2; jy++)
            #pragma unroll
            for (int jx = 0; jx < 2; jx++, k++) {
                const int ix = xs[jx], iy = ys[jy];
                const bool v = (ix >= 0) && (ix < IMW) && (iy >= 0) && (iy < IMH);
                const int icx = min(max(ix, 0), IMW - 1);
                const int icy = min(max(iy, 0), IMH - 1);
                off[l][k] = icy * IMW + icx;
                wv[l][k]  = v ? a * wx[jx] * wy[jy] : 0.0f;
            }
    }

    const size_t opix = (size_t)yy * IMW + xx;
    #pragma unroll 2
    for (int c = 0; c < CH; c++) {
        float s = 0.0f;
        #pragma unroll
        for (int l = 0; l < L_SZ; l++) {
            const float* ic = x + ((size_t)(b * L_SZ + l) * CH + c) * HW;
            s += wv[l][0] * ic[off[l][0]] + wv[l][1] * ic[off[l][1]]
               + wv[l][2] * ic[off[l][2]] + wv[l][3] * ic[off[l][3]];
        }
        out[((size_t)b * CH + c) * HW + opix] = s;
    }
}

// ---------------- launch ----------------
extern "C" void kernel_launch(void* const* d_in, const int* in_sizes, int n_in,
                              void* d_out, int out_size)
{
    const float* x    = (const float*)d_in[0];
    const float* nam  = (const float*)d_in[2];
    const float* w1   = (const float*)d_in[3];
    const float* b1   = (const float*)d_in[4];
    const float* w2   = (const float*)d_in[5];
    const float* b2   = (const float*)d_in[6];
    const float* w3   = (const float*)d_in[7];
    const float* b3   = (const float*)d_in[8];
    const float* kf1w = (const float*)d_in[9];
    const float* kf1b = (const float*)d_in[10];
    const float* kf2w = (const float*)d_in[11];
    const float* kf2b = (const float*)d_in[12];
    const float* kf3w = (const float*)d_in[13];
    const float* kf3b = (const float*)d_in[14];
    const float* qf1w = (const float*)d_in[15];
    const float* qf1b = (const float*)d_in[16];
    const float* qf2w = (const float*)d_in[17];
    const float* qf2b = (const float*)d_in[18];
    const float* qf3w = (const float*)d_in[19];
    const float* qf3b = (const float*)d_in[20];
    const float* aw   = (const float*)d_in[21];
    const float* ab   = (const float*)d_in[22];

    unsigned *p_nbf, *p_c1bf, *p_c2bf;
    float *p_c3;
    cudaGetSymbolAddress((void**)&p_nbf, g_nbf);
    cudaGetSymbolAddress((void**)&p_c1bf, g_c1bf);
    cudaGetSymbolAddress((void**)&p_c2bf, g_c2bf);
    cudaGetSymbolAddress((void**)&p_c3, g_c3);

    // dynamic smem (bytes): (INR*WP*12 + 16*COUTB*8) * 4
    constexpr int SM1 = (6  * 130 * 12 + 16 * 32 * 8) * 4;   // 53,824
    constexpr int SM2 = (10 * 66  * 12 + 16 * 32 * 8) * 4;   // 48,064
    constexpr int SM3 = (18 * 34  * 12 + 16 * 16 * 8) * 4;   // 37,568

    cudaFuncSetAttribute((const void*)conv_bf16<64, 32, 256, 128, 32, true>,
                         cudaFuncAttributeMaxDynamicSharedMemorySize, SM1);
    cudaFuncSetAttribute((const void*)conv_bf16<32, 64, 128, 64, 32, true>,
                         cudaFuncAttributeMaxDynamicSharedMemorySize, SM2);
    cudaFuncSetAttribute((const void*)conv_bf16<64, 64, 64, 32, 16, false>,
                         cudaFuncAttributeMaxDynamicSharedMemorySize, SM3);

    sample_kernel<<<dim3(IMH, NIMG), IMW>>>(x, nam);

    conv_bf16<64, 32, 256, 128, 32, true><<<dim3(64, NIMG, 1), 256, SM1>>>(
        p_nbf, w1, b1, nullptr, p_c1bf);
    conv_bf16<32, 64, 128, 64, 32, true><<<dim3(16, NIMG, 2), 256, SM2>>>(
        p_c1bf, w2, b2, nullptr, p_c2bf);
    conv_bf16<64, 64, 64, 32, 16, false><<<dim3(4, NIMG, 4), 256, SM3>>>(
        p_c2bf, w3, b3, p_c3, nullptr);

    pool_kernel<<<160, 256>>>();
    attn_kernel<<<B_SZ, 256>>>(kf1w, kf1b, kf2w, kf2b, kf3w, kf3b,
                               qf1w, qf1b, qf2w, qf2b, qf3w, qf3b, aw, ab);
    fuse_kernel<<<dim3(IMH, B_SZ), IMW>>>((float*)d_out, x, nam);
}

// round 9
// speedup vs baseline: 1.2194x; 1.2194x over previous
#include <cuda_runtime.h>
#include <math.h>
#include <stdint.h>

// Problem constants
#define B_SZ   4
#define L_SZ   5
#define NIMG   20          // B*L
#define CH     64
#define IMH    256
#define IMW    128
#define HW     (IMH*IMW)   // 32768

// ---------------- scratch (static device globals; no allocation) ----------------
__device__ float    g_neigh[NIMG * CH * HW];          // fp32 sampled input (for fuse)
__device__ unsigned g_nbf[NIMG * 32 * HW];            // sampled input, bf16 pairs (for conv1)
__device__ unsigned g_c1bf[NIMG * 16 * 128 * 64];     // conv1 out bf16 pairs
__device__ unsigned g_c2bf[NIMG * 32 * 64 * 32];      // conv2 out bf16 pairs
__device__ float    g_c3[NIMG * 64 * 32 * 16];        // conv3 out fp32
__device__ float    g_pool[NIMG * 64];
__device__ float    g_attn[B_SZ * L_SZ];

// ---------------- helpers ----------------
__device__ __forceinline__ unsigned pack_bf16(float lo, float hi) {
    unsigned u;
    asm("cvt.rn.bf16x2.f32 %0, %1, %2;" : "=r"(u) : "f"(hi), "f"(lo));
    return u;
}
__device__ __forceinline__ int pcmap(int p) { return ((p & 3) << 1) | (p >> 2); }

// ---------------- Kernel 1: affine grid + bilinear sample -> fp32 + bf16 pairs ----------------
__global__ void sample_kernel(const float* __restrict__ x, const float* __restrict__ nam)
{
    const int n  = blockIdx.y;
    const int yy = blockIdx.x;
    const int xx = threadIdx.x;
    const int b  = n / L_SZ, l = n % L_SZ;

    const float* th = nam + (b * 25 + l) * 6;
    const float t00 = th[0], t01 = th[1], t02 = th[2];
    const float t10 = th[3], t11 = th[4], t12 = th[5];

    const float gxn = (xx + 0.5f) * (2.0f / IMW) - 1.0f;
    const float gyn = (yy + 0.5f) * (2.0f / IMH) - 1.0f;
    const float gx = t00 * gxn + t01 * gyn + t02;
    const float gy = t10 * gxn + t11 * gyn + t12;
    const float sx = ((gx + 1.0f) * IMW - 1.0f) * 0.5f;
    const float sy = ((gy + 1.0f) * IMH - 1.0f) * 0.5f;

    const float x0f = floorf(sx), y0f = floorf(sy);
    const float fx = sx - x0f, fy = sy - y0f;
    const int x0 = (int)x0f, y0 = (int)y0f;

    const int   xs[2] = { x0, x0 + 1 };
    const int   ys[2] = { y0, y0 + 1 };
    const float wx[2] = { 1.0f - fx, fx };
    const float wy[2] = { 1.0f - fy, fy };

    int   off[4];
    float wv[4];
    int k = 0;
    #pragma unroll
    for (int jy = 0; jy < 2; jy++)
        #pragma unroll
        for (int jx = 0; jx < 2; jx++, k++) {
            const int ix = xs[jx], iy = ys[jy];
            const bool v = (ix >= 0) && (ix < IMW) && (iy >= 0) && (iy < IMH);
            const int icx = min(max(ix, 0), IMW - 1);
            const int icy = min(max(iy, 0), IMH - 1);
            off[k] = icy * IMW + icx;
            wv[k]  = v ? wx[jx] * wy[jy] : 0.0f;
        }

    const float* img = x + (size_t)n * CH * HW;
    const size_t pix = (size_t)yy * IMW + xx;
    float*    dstf = g_neigh + (size_t)n * CH * HW + pix;
    unsigned* dstu = g_nbf  + (size_t)n * 32 * HW + pix;
    #pragma unroll 4
    for (int p = 0; p < 32; p++) {
        const float* i0 = img + (size_t)(2 * p) * HW;
        const float* i1 = i0 + HW;
        const float v0 = wv[0]*i0[off[0]] + wv[1]*i0[off[1]] + wv[2]*i0[off[2]] + wv[3]*i0[off[3]];
        const float v1 = wv[0]*i1[off[0]] + wv[1]*i1[off[1]] + wv[2]*i1[off[2]] + wv[3]*i1[off[3]];
        dstf[(size_t)(2 * p) * HW]     = v0;
        dstf[(size_t)(2 * p + 1) * HW] = v1;
        dstu[(size_t)p * HW] = pack_bf16(v0, v1);
    }
}

// ---------------- bf16 tensor-core conv 4x4 s2 p1 + bias + relu, double-buffered ----------------
// m16n8k16: M=128 positions/CTA, N=COUTB, K chunk = 16 cins (8 bf16 pairs).
// Double-buffered smem: per chunk [LOAD(k+1)->regs | MMA(k,buf) | STORE(k+1,~buf) | 1 sync].
template<int CIN, int COUT, int IH, int IW, int COUTB, bool OBF>
__global__ __launch_bounds__(256, 2)
void conv_bf16(const unsigned* __restrict__ in, const float* __restrict__ wgt,
               const float* __restrict__ bias, float* __restrict__ outf,
               unsigned* __restrict__ outu)
{
    constexpr int OH   = IH / 2, OW = IW / 2;
    constexpr int ROWS = 128 / OW;
    constexpr int INR  = 2 * ROWS + 2;
    constexpr int WP   = IW + 2;
    constexpr int AP   = 12;                 // uint pitch per input position
    constexpr int CP2  = CIN / 2;            // total cin pairs
    constexpr int NC   = CP2 / 8;            // chunks
    constexpr int NT   = COUTB / 8;
    constexpr int SPR  = OW / 16;
    constexpr int SINU = INR * WP * AP;      // smem uints per input buffer
    constexpr int SWU  = 16 * COUTB * 8;     // smem uints per weight buffer
    constexpr int LIN  = 8 * INR * WP;       // staged input elements per chunk
    constexpr int NI   = (LIN + 255) / 256;
    constexpr int NWU  = SWU / 256;
    static_assert(ROWS * OW == 128 && 8 % SPR == 0, "tiling");

    extern __shared__ unsigned smu[];
    unsigned* s_win = smu;                   // [2][SINU]
    unsigned* s_w   = smu + 2 * SINU;        // [2][SWU]

    const int n     = blockIdx.y;
    const int oy0   = blockIdx.x * ROWS;
    const int cbase = blockIdx.z * COUTB;
    const int t     = threadIdx.x;
    const int warp  = t >> 5;
    const int lane  = t & 31;

    const int row_local = warp / SPR;
    const int ox0       = (warp % SPR) * 16;
    const int qid       = lane >> 2;
    const int ci0       = lane & 3;

    float acc[NT][4];
    #pragma unroll
    for (int j = 0; j < NT; j++)
        #pragma unroll
        for (int p = 0; p < 4; p++) acc[j][p] = 0.0f;

    const unsigned* inN = in + (size_t)n * CP2 * IH * IW;
    const int y0 = 2 * oy0 - 1;

    unsigned rin[NI];
    unsigned rwu[NWU];

    auto LOAD = [&](int c) {                 // chunk index; pair base = 8c
        const int cb2 = c * 8;
        #pragma unroll
        for (int i = 0; i < NI; i++) {
            const int idx = t + i * 256;
            unsigned v = 0u;
            if (idx < LIN) {
                const int p   = idx / (INR * WP);
                const int rem = idx % (INR * WP);
                const int rr  = rem / WP, col = rem % WP;
                const int iy = y0 + rr, ix = col - 1;
                if (iy >= 0 && iy < IH && (unsigned)ix < (unsigned)IW)
                    v = inN[(size_t)(cb2 + p) * IH * IW + (size_t)iy * IW + ix];
            }
            rin[i] = v;
        }
        #pragma unroll
        for (int i = 0; i < NWU; i++) {
            const int idx = t + i * 256;
            const int o = idx >> 7, rem = idx & 127;
            const int p = rem >> 4, tap = rem & 15;
            const float f0 = wgt[(size_t)(cbase + o) * CIN * 16 + (size_t)(2 * (cb2 + p)) * 16 + tap];
            const float f1 = wgt[(size_t)(cbase + o) * CIN * 16 + (size_t)(2 * (cb2 + p) + 1) * 16 + tap];
            rwu[i] = pack_bf16(f0, f1);
        }
    };
    auto STORE = [&](int c) {                // store staged regs into buffer c&1
        unsigned* dw = s_win + (c & 1) * SINU;
        unsigned* ww = s_w   + (c & 1) * SWU;
        #pragma unroll
        for (int i = 0; i < NI; i++) {
            const int idx = t + i * 256;
            if (idx < LIN) {
                const int p   = idx / (INR * WP);
                const int rem = idx % (INR * WP);
                dw[rem * AP + pcmap(p)] = rin[i];
            }
        }
        #pragma unroll
        for (int i = 0; i < NWU; i++) {
            const int idx = t + i * 256;
            const int o = idx >> 7, rem = idx & 127;
            const int p = rem >> 4, tap = rem & 15;
            ww[(tap * COUTB + o) * 8 + pcmap(p)] = rwu[i];
        }
    };

    LOAD(0);
    STORE(0);
    __syncthreads();

    for (int c = 0; c < NC; c++) {
        const bool more = (c + 1 < NC);
        if (more) LOAD(c + 1);

        const unsigned* bw = s_win + (c & 1) * SINU;
        const unsigned* wb = s_w   + (c & 1) * SWU;
        #pragma unroll
        for (int ky = 0; ky < 4; ky++) {
            const unsigned* rowp = &bw[((2 * row_local + ky) * WP + 2 * (ox0 + qid)) * AP + 2 * ci0];
            #pragma unroll
            for (int kx = 0; kx < 4; kx++) {
                const uint2 A0 = *(const uint2*)(rowp + kx * AP);          // {a0, a2}
                const uint2 A1 = *(const uint2*)(rowp + (kx + 16) * AP);   // {a1, a3}
                const int tap = ky * 4 + kx;
                #pragma unroll
                for (int j = 0; j < NT; j++) {
                    const uint2 Bv = *(const uint2*)&wb[(tap * COUTB + j * 8 + qid) * 8 + 2 * ci0];
                    asm volatile(
                        "mma.sync.aligned.m16n8k16.row.col.f32.bf16.bf16.f32 "
                        "{%0,%1,%2,%3}, {%4,%5,%6,%7}, {%8,%9}, {%0,%1,%2,%3};"
                        : "+f"(acc[j][0]), "+f"(acc[j][1]), "+f"(acc[j][2]), "+f"(acc[j][3])
                        : "r"(A0.x), "r"(A1.x), "r"(A0.y), "r"(A1.y),
                          "r"(Bv.x), "r"(Bv.y));
                }
            }
        }
        if (more) {
            STORE(c + 1);                    // opposite buffer; safe vs in-flight MMA(c)
            __syncthreads();
        }
    }

    // epilogue: bias + relu
    const int oy = oy0 + row_local;
    const int ox = ox0 + qid;
    #pragma unroll
    for (int j = 0; j < NT; j++) {
        const int c0i = cbase + j * 8 + 2 * ci0;
        const float bv0 = bias[c0i], bv1 = bias[c0i + 1];
        const float v0 = fmaxf(acc[j][0] + bv0, 0.0f);
        const float v1 = fmaxf(acc[j][1] + bv1, 0.0f);
        const float v2 = fmaxf(acc[j][2] + bv0, 0.0f);
        const float v3 = fmaxf(acc[j][3] + bv1, 0.0f);
        if (OBF) {
            const int gp = (cbase >> 1) + j * 4 + ci0;
            unsigned* ob = outu + ((size_t)n * (COUT / 2) + gp) * OH * OW + (size_t)oy * OW;
            ob[ox]     = pack_bf16(v0, v1);
            ob[ox + 8] = pack_bf16(v2, v3);
        } else {
            float* o0 = outf + (((size_t)n * COUT + c0i) * OH + oy) * OW;
            float* o1 = outf + (((size_t)n * COUT + c0i + 1) * OH + oy) * OW;
            o0[ox]     = v0;
            o1[ox]     = v1;
            o0[ox + 8] = v2;
            o1[ox + 8] = v3;
        }
    }
}

// ---------------- mean pool: one warp per (n, c) reduction over 512 ----------------
__global__ void pool_kernel()
{
    const int gw   = (blockIdx.x * blockDim.x + threadIdx.x) >> 5;
    const int lane = threadIdx.x & 31;
    const float4* p = (const float4*)(g_c3 + (size_t)gw * 512);
    float s = 0.0f;
    #pragma unroll
    for (int i = lane; i < 128; i += 32) {
        const float4 v = p[i];
        s += (v.x + v.y) + (v.z + v.w);
    }
    #pragma unroll
    for (int o = 16; o; o >>= 1) s += __shfl_xor_sync(0xffffffffu, s, o);
    if (lane == 0) g_pool[gw] = s * (1.0f / 512.0f);
}

// ---------------- attention: MLPs + softmax ----------------
__global__ void attn_kernel(const float* __restrict__ kf1w, const float* __restrict__ kf1b,
                            const float* __restrict__ kf2w, const float* __restrict__ kf2b,
                            const float* __restrict__ kf3w, const float* __restrict__ kf3b,
                            const float* __restrict__ qf1w, const float* __restrict__ qf1b,
                            const float* __restrict__ qf2w, const float* __restrict__ qf2b,
                            const float* __restrict__ qf3w, const float* __restrict__ qf3b,
                            const float* __restrict__ aw,   const float* __restrict__ ab)
{
    const int b = blockIdx.x;
    const int t = threadIdx.x;

    __shared__ float pooled[L_SZ][64];
    __shared__ float h1[L_SZ][256];
    __shared__ float h2[L_SZ][128];
    __shared__ float keys[L_SZ][256];
    __shared__ float q1[256], q2[128], qv[32], qq[256];
    __shared__ float logit[L_SZ];

    for (int idx = t; idx < L_SZ * 64; idx += 256) {
        const int l = idx / 64, c = idx % 64;
        pooled[l][c] = g_pool[(b * L_SZ + l) * 64 + c];
    }
    __syncthreads();

    for (int idx = t; idx < L_SZ * 256; idx += 256) {
        const int l = idx / 256, o = idx % 256;
        float s = kf1b[o];
        for (int i = 0; i < 64; i++) s = fmaf(pooled[l][i], kf1w[o * 64 + i], s);
        h1[l][o] = fmaxf(s, 0.0f);
    }
    __syncthreads();
    for (int idx = t; idx < L_SZ * 128; idx += 256) {
        const int l = idx / 128, o = idx % 128;
        float s = kf2b[o];
        for (int i = 0; i < 256; i++) s = fmaf(h1[l][i], kf2w[o * 256 + i], s);
        h2[l][o] = fmaxf(s, 0.0f);
    }
    __syncthreads();
    for (int idx = t; idx < L_SZ * 256; idx += 256) {
        const int l = idx / 256, o = idx % 256;
        float s = kf3b[o];
        for (int i = 0; i < 128; i++) s = fmaf(h2[l][i], kf3w[o * 128 + i], s);
        keys[l][o] = s;
    }
    __syncthreads();

    {
        float s = qf1b[t];
        for (int i = 0; i < 64; i++) s = fmaf(pooled[0][i], qf1w[t * 64 + i], s);
        q1[t] = fmaxf(s, 0.0f);
    }
    __syncthreads();
    if (t < 128) {
        float s = qf2b[t];
        for (int i = 0; i < 256; i++) s = fmaf(q1[i], qf2w[t * 256 + i], s);
        q2[t] = fmaxf(s, 0.0f);
    }
    __syncthreads();
    if (t < 32) {
        float s = qf3b[t];
        for (int i = 0; i < 128; i++) s = fmaf(q2[i], qf3w[t * 128 + i], s);
        qv[t] = s;
    }
    __syncthreads();
    {
        float s = ab[t];
        for (int i = 0; i < 32; i++) s = fmaf(qv[i], aw[t * 32 + i], s);
        qq[t] = s;
    }
    __syncthreads();
    if (t < L_SZ) {
        float s = 0.0f;
        for (int i = 0; i < 256; i++) s = fmaf(keys[t][i], qq[i], s);
        logit[t] = s;
    }
    __syncthreads();
    if (t == 0) {
        float m = logit[0];
        for (int l = 1; l < L_SZ; l++) m = fmaxf(m, logit[l]);
        float e[L_SZ], ssum = 0.0f;
        for (int l = 0; l < L_SZ; l++) { e[l] = expf(logit[l] - m); ssum += e[l]; }
        const float inv = 1.0f / ssum;
        for (int l = 0; l < L_SZ; l++) g_attn[b * L_SZ + l] = e[l] * inv;
    }
}

// ---------------- fuse: attention-weighted sum of fp32 neigh ----------------
__global__ void fuse_kernel(float* __restrict__ out)
{
    const size_t i = (size_t)blockIdx.x * blockDim.x + threadIdx.x;
    const size_t per_b = (size_t)CH * HW / 4;
    const int b = (int)(i / per_b);
    const size_t rem = i % per_b;

    float a[L_SZ];
    #pragma unroll
    for (int l = 0; l < L_SZ; l++) a[l] = g_attn[b * L_SZ + l];

    const float4* nv = (const float4*)g_neigh;
    float4 s = make_float4(0.f, 0.f, 0.f, 0.f);
    #pragma unroll
    for (int l = 0; l < L_SZ; l++) {
        const float4 v = nv[(size_t)(b * L_SZ + l) * per_b + rem];
        s.x = fmaf(a[l], v.x, s.x);
        s.y = fmaf(a[l], v.y, s.y);
        s.z = fmaf(a[l], v.z, s.z);
        s.w = fmaf(a[l], v.w, s.w);
    }
    ((float4*)out)[i] = s;
}

// ---------------- launch ----------------
extern "C" void kernel_launch(void* const* d_in, const int* in_sizes, int n_in,
                              void* d_out, int out_size)
{
    const float* x    = (const float*)d_in[0];
    const float* nam  = (const float*)d_in[2];
    const float* w1   = (const float*)d_in[3];
    const float* b1   = (const float*)d_in[4];
    const float* w2   = (const float*)d_in[5];
    const float* b2   = (const float*)d_in[6];
    const float* w3   = (const float*)d_in[7];
    const float* b3   = (const float*)d_in[8];
    const float* kf1w = (const float*)d_in[9];
    const float* kf1b = (const float*)d_in[10];
    const float* kf2w = (const float*)d_in[11];
    const float* kf2b = (const float*)d_in[12];
    const float* kf3w = (const float*)d_in[13];
    const float* kf3b = (const float*)d_in[14];
    const float* qf1w = (const float*)d_in[15];
    const float* qf1b = (const float*)d_in[16];
    const float* qf2w = (const float*)d_in[17];
    const float* qf2b = (const float*)d_in[18];
    const float* qf3w = (const float*)d_in[19];
    const float* qf3b = (const float*)d_in[20];
    const float* aw   = (const float*)d_in[21];
    const float* ab   = (const float*)d_in[22];

    unsigned *p_nbf, *p_c1bf, *p_c2bf;
    float *p_c3;
    cudaGetSymbolAddress((void**)&p_nbf, g_nbf);
    cudaGetSymbolAddress((void**)&p_c1bf, g_c1bf);
    cudaGetSymbolAddress((void**)&p_c2bf, g_c2bf);
    cudaGetSymbolAddress((void**)&p_c3, g_c3);

    // double-buffered dynamic smem (bytes): 2*(INR*WP*12 + 16*COUTB*8)*4
    constexpr int SM1 = 2 * (6  * 130 * 12 + 16 * 32 * 8) * 4;   // 107,648
    constexpr int SM2 = 2 * (10 * 66  * 12 + 16 * 32 * 8) * 4;   //  96,128
    constexpr int SM3 = 2 * (18 * 34  * 12 + 16 * 16 * 8) * 4;   //  75,136

    cudaFuncSetAttribute((const void*)conv_bf16<64, 32, 256, 128, 32, true>,
                         cudaFuncAttributeMaxDynamicSharedMemorySize, SM1);
    cudaFuncSetAttribute((const void*)conv_bf16<32, 64, 128, 64, 32, true>,
                         cudaFuncAttributeMaxDynamicSharedMemorySize, SM2);
    cudaFuncSetAttribute((const void*)conv_bf16<64, 64, 64, 32, 16, false>,
                         cudaFuncAttributeMaxDynamicSharedMemorySize, SM3);

    sample_kernel<<<dim3(IMH, NIMG), IMW>>>(x, nam);

    conv_bf16<64, 32, 256, 128, 32, true><<<dim3(64, NIMG, 1), 256, SM1>>>(
        p_nbf, w1, b1, nullptr, p_c1bf);
    conv_bf16<32, 64, 128, 64, 32, true><<<dim3(16, NIMG, 2), 256, SM2>>>(
        p_c1bf, w2, b2, nullptr, p_c2bf);
    conv_bf16<64, 64, 64, 32, 16, false><<<dim3(4, NIMG, 4), 256, SM3>>>(
        p_c2bf, w3, b3, p_c3, nullptr);

    pool_kernel<<<160, 256>>>();
    attn_kernel<<<B_SZ, 256>>>(kf1w, kf1b, kf2w, kf2b, kf3w, kf3b,
                               qf1w, qf1b, qf2w, qf2b, qf3w, qf3b, aw, ab);
    const size_t n4 = (size_t)B_SZ * CH * HW / 4;
    fuse_kernel<<<(unsigned)(n4 / 256), 256>>>((float*)d_out);
}

// round 14
// speedup vs baseline: 1.7656x; 1.4479x over previous
#include <cuda_runtime.h>
#include <math.h>
#include <stdint.h>

// Problem constants
#define B_SZ   4
#define L_SZ   5
#define NIMG   20          // B*L
#define CH     64
#define IMH    256
#define IMW    128
#define HW     (IMH*IMW)   // 32768

// ---------------- scratch (static device globals; no allocation) ----------------
__device__ float    g_neigh[NIMG * CH * HW];          // fp32 sampled input
__device__ unsigned g_c1bf[NIMG * 16 * 128 * 64];     // conv1 out bf16 pairs
__device__ unsigned g_c2bf[NIMG * 32 * 64 * 32];      // conv2 out bf16 pairs
__device__ float    g_c3[NIMG * 64 * 32 * 16];        // conv3 out fp32
__device__ float    g_pool[NIMG * 64];
__device__ float    g_attn[B_SZ * L_SZ];

// ---------------- helpers ----------------
__device__ __forceinline__ unsigned pack_bf16(float lo, float hi) {
    unsigned u;
    asm("cvt.rn.bf16x2.f32 %0, %1, %2;" : "=r"(u) : "f"(hi), "f"(lo));
    return u;
}
__device__ __forceinline__ int pcmap(int p) { return ((p & 3) << 1) | (p >> 2); }

// ---------------- Kernel 1: affine grid + bilinear sample -> fp32 ----------------
__global__ void sample_kernel(const float* __restrict__ x, const float* __restrict__ nam)
{
    const int n  = blockIdx.y;
    const int yy = blockIdx.x;
    const int xx = threadIdx.x;
    const int b  = n / L_SZ, l = n % L_SZ;

    const float* th = nam + (b * 25 + l) * 6;
    const float t00 = th[0], t01 = th[1], t02 = th[2];
    const float t10 = th[3], t11 = th[4], t12 = th[5];

    const float gxn = (xx + 0.5f) * (2.0f / IMW) - 1.0f;
    const float gyn = (yy + 0.5f) * (2.0f / IMH) - 1.0f;
    const float gx = t00 * gxn + t01 * gyn + t02;
    const float gy = t10 * gxn + t11 * gyn + t12;
    const float sx = ((gx + 1.0f) * IMW - 1.0f) * 0.5f;
    const float sy = ((gy + 1.0f) * IMH - 1.0f) * 0.5f;

    const float x0f = floorf(sx), y0f = floorf(sy);
    const float fx = sx - x0f, fy = sy - y0f;
    const int x0 = (int)x0f, y0 = (int)y0f;

    const int   xs[2] = { x0, x0 + 1 };
    const int   ys[2] = { y0, y0 + 1 };
    const float wx[2] = { 1.0f - fx, fx };
    const float wy[2] = { 1.0f - fy, fy };

    int   off[4];
    float wv[4];
    int k = 0;
    #pragma unroll
    for (int jy = 0; jy < 2; jy++)
        #pragma unroll
        for (int jx = 0; jx < 2; jx++, k++) {
            const int ix = xs[jx], iy = ys[jy];
            const bool v = (ix >= 0) && (ix < IMW) && (iy >= 0) && (iy < IMH);
            const int icx = min(max(ix, 0), IMW - 1);
            const int icy = min(max(iy, 0), IMH - 1);
            off[k] = icy * IMW + icx;
            wv[k]  = v ? wx[jx] * wy[jy] : 0.0f;
        }

    const float* img = x + (size_t)n * CH * HW;
    float* dst = g_neigh + (size_t)n * CH * HW + yy * IMW + xx;
    #pragma unroll 4
    for (int c = 0; c < CH; c++) {
        const float* ic = img + c * HW;
        const float v = wv[0] * ic[off[0]] + wv[1] * ic[off[1]]
                      + wv[2] * ic[off[2]] + wv[3] * ic[off[3]];
        dst[c * HW] = v;
    }
}

// ---------------- bf16 tensor-core conv 4x4 s2 p1 + bias + relu ----------------
// m16n8k16, M=128 positions/CTA, N=COUTB, chunk = 16 cins (8 bf16 pairs).
// ALL staging indices (input spatial offset, smem offset, weight offsets) are
// precomputed ONCE; per chunk staging is [add + LDG] / [STS] only. Double-buffered.
// INF32: input is fp32 planes (conv1, packs pairs on the fly); else bf16 pairs.
template<int CIN, int COUT, int IH, int IW, int COUTB, bool INF32, bool OBF>
__global__ __launch_bounds__(256, 2)
void conv_bf16(const void* __restrict__ inv, const float* __restrict__ wgt,
               const float* __restrict__ bias, float* __restrict__ outf,
               unsigned* __restrict__ outu)
{
    constexpr int OH   = IH / 2, OW = IW / 2;
    constexpr int ROWS = 128 / OW;
    constexpr int INR  = 2 * ROWS + 2;
    constexpr int WP   = IW + 2;
    constexpr int AP   = 12;                 // uint pitch per input position
    constexpr int CP2  = CIN / 2;            // cin pairs
    constexpr int NC   = CP2 / 8;            // chunks
    constexpr int NT   = COUTB / 8;
    constexpr int SPR  = OW / 16;
    constexpr int SINU = INR * WP * AP;
    constexpr int SWU  = 16 * COUTB * 8;
    constexpr int LIN  = 8 * INR * WP;       // staged elements (pairs) per chunk
    constexpr int NI   = (LIN + 255) / 256;
    constexpr int NWU  = SWU / 256;
    constexpr int PSTR = INF32 ? 2 * IH * IW : IH * IW;   // plane stride per pair
    static_assert(ROWS * OW == 128 && 8 % SPR == 0, "tiling");

    extern __shared__ unsigned smu[];
    unsigned* s_win = smu;                   // [2][SINU]
    unsigned* s_w   = smu + 2 * SINU;        // [2][SWU]

    const int n     = blockIdx.y;
    const int oy0   = blockIdx.x * ROWS;
    const int cbase = blockIdx.z * COUTB;
    const int t     = threadIdx.x;
    const int warp  = t >> 5;
    const int lane  = t & 31;

    const int row_local = warp / SPR;
    const int ox0       = (warp % SPR) * 16;
    const int qid       = lane >> 2;
    const int ci0       = lane & 3;

    float acc[NT][4];
    #pragma unroll
    for (int j = 0; j < NT; j++)
        #pragma unroll
        for (int p = 0; p < 4; p++) acc[j][p] = 0.0f;

    const float*    inF = (const float*)inv    + (size_t)n * CIN * IH * IW;
    const unsigned* inU = (const unsigned*)inv + (size_t)n * CP2 * IH * IW;
    const int y0 = 2 * oy0 - 1;

    // ---- one-time index precompute (chunk-invariant) ----
    int src_sp[NI], smoff[NI];
    #pragma unroll
    for (int i = 0; i < NI; i++) {
        const int idx = t + i * 256;
        int ss = -1, so = -1;
        if (idx < LIN) {
            const int p   = idx / (INR * WP);
            const int rem = idx % (INR * WP);
            const int rr  = rem / WP, col = rem % WP;
            const int iy = y0 + rr, ix = col - 1;
            so = rem * AP + pcmap(p);
            if (iy >= 0 && iy < IH && (unsigned)ix < (unsigned)IW)
                ss = p * PSTR + iy * IW + ix;
        }
        src_sp[i] = ss; smoff[i] = so;
    }
    int woff[NWU], wsoff[NWU];
    #pragma unroll
    for (int i = 0; i < NWU; i++) {
        const int idx = t + i * 256;
        const int o = idx >> 7, rem = idx & 127;
        const int p = rem >> 4, tap = rem & 15;
        woff[i]  = (cbase + o) * CIN * 16 + 32 * p + tap;
        wsoff[i] = (tap * COUTB + o) * 8 + pcmap(p);
    }

    unsigned rin[NI];
    unsigned rwu[NWU];

    auto LOAD = [&](int c) {
        const int ibase = c * 8 * PSTR;
        const int wbase = c * 8 * 32;
        #pragma unroll
        for (int i = 0; i < NI; i++) {
            unsigned v = 0u;
            if (src_sp[i] >= 0) {
                if (INF32) {
                    const float f0 = inF[ibase + src_sp[i]];
                    const float f1 = inF[ibase + src_sp[i] + IH * IW];
                    v = pack_bf16(f0, f1);
                } else {
                    v = inU[ibase + src_sp[i]];
                }
            }
            rin[i] = v;
        }
        #pragma unroll
        for (int i = 0; i < NWU; i++)
            rwu[i] = pack_bf16(wgt[woff[i] + wbase], wgt[woff[i] + wbase + 16]);
    };
    auto STORE = [&](int c) {
        unsigned* dw = s_win + (c & 1) * SINU;
        unsigned* ww = s_w   + (c & 1) * SWU;
        #pragma unroll
        for (int i = 0; i < NI; i++)
            if (smoff[i] >= 0) dw[smoff[i]] = rin[i];
        #pragma unroll
        for (int i = 0; i < NWU; i++)
            ww[wsoff[i]] = rwu[i];
    };

    LOAD(0);
    STORE(0);
    __syncthreads();

    for (int c = 0; c < NC; c++) {
        const bool more = (c + 1 < NC);
        if (more) LOAD(c + 1);

        const unsigned* bw = s_win + (c & 1) * SINU;
        const unsigned* wb = s_w   + (c & 1) * SWU;
        #pragma unroll
        for (int ky = 0; ky < 4; ky++) {
            const unsigned* rowp = &bw[((2 * row_local + ky) * WP + 2 * (ox0 + qid)) * AP + 2 * ci0];
            #pragma unroll
            for (int kx = 0; kx < 4; kx++) {
                const uint2 A0 = *(const uint2*)(rowp + kx * AP);          // {a0, a2}
                const uint2 A1 = *(const uint2*)(rowp + (kx + 16) * AP);   // {a1, a3}
                const int tap = ky * 4 + kx;
                #pragma unroll
                for (int j = 0; j < NT; j++) {
                    const uint2 Bv = *(const uint2*)&wb[(tap * COUTB + j * 8 + qid) * 8 + 2 * ci0];
                    asm volatile(
                        "mma.sync.aligned.m16n8k16.row.col.f32.bf16.bf16.f32 "
                        "{%0,%1,%2,%3}, {%4,%5,%6,%7}, {%8,%9}, {%0,%1,%2,%3};"
                        : "+f"(acc[j][0]), "+f"(acc[j][1]), "+f"(acc[j][2]), "+f"(acc[j][3])
                        : "r"(A0.x), "r"(A1.x), "r"(A0.y), "r"(A1.y),
                          "r"(Bv.x), "r"(Bv.y));
                }
            }
        }
        if (more) {
            STORE(c + 1);                    // opposite buffer; safe vs in-flight MMA(c)
            __syncthreads();
        }
    }

    // epilogue: bias + relu
    const int oy = oy0 + row_local;
    const int ox = ox0 + qid;
    #pragma unroll
    for (int j = 0; j < NT; j++) {
        const int c0i = cbase + j * 8 + 2 * ci0;
        const float bv0 = bias[c0i], bv1 = bias[c0i + 1];
        const float v0 = fmaxf(acc[j][0] + bv0, 0.0f);
        const float v1 = fmaxf(acc[j][1] + bv1, 0.0f);
        const float v2 = fmaxf(acc[j][2] + bv0, 0.0f);
        const float v3 = fmaxf(acc[j][3] + bv1, 0.0f);
        if (OBF) {
            const int gp = (cbase >> 1) + j * 4 + ci0;
            unsigned* ob = outu + ((size_t)n * (COUT / 2) + gp) * OH * OW + oy * OW;
            ob[ox]     = pack_bf16(v0, v1);
            ob[ox + 8] = pack_bf16(v2, v3);
        } else {
            float* o0 = outf + (((size_t)n * COUT + c0i) * OH + oy) * OW;
            float* o1 = outf + (((size_t)n * COUT + c0i + 1) * OH + oy) * OW;
            o0[ox]     = v0;
            o1[ox]     = v1;
            o0[ox + 8] = v2;
            o1[ox + 8] = v3;
        }
    }
}

// ---------------- mean pool: one warp per (n, c) reduction over 512 ----------------
__global__ void pool_kernel()
{
    const int gw   = (blockIdx.x * blockDim.x + threadIdx.x) >> 5;
    const int lane = threadIdx.x & 31;
    const float4* p = (const float4*)(g_c3 + (size_t)gw * 512);
    float s = 0.0f;
    #pragma unroll
    for (int i = lane; i < 128; i += 32) {
        const float4 v = p[i];
        s += (v.x + v.y) + (v.z + v.w);
    }
    #pragma unroll
    for (int o = 16; o; o >>= 1) s += __shfl_xor_sync(0xffffffffu, s, o);
    if (lane == 0) g_pool[gw] = s * (1.0f / 512.0f);
}

// ---------------- attention: MLPs + softmax ----------------
__global__ void attn_kernel(const float* __restrict__ kf1w, const float* __restrict__ kf1b,
                            const float* __restrict__ kf2w, const float* __restrict__ kf2b,
                            const float* __restrict__ kf3w, const float* __restrict__ kf3b,
                            const float* __restrict__ qf1w, const float* __restrict__ qf1b,
                            const float* __restrict__ qf2w, const float* __restrict__ qf2b,
                            const float* __restrict__ qf3w, const float* __restrict__ qf3b,
                            const float* __restrict__ aw,   const float* __restrict__ ab)
{
    const int b = blockIdx.x;
    const int t = threadIdx.x;

    __shared__ float pooled[L_SZ][64];
    __shared__ float h1[L_SZ][256];
    __shared__ float h2[L_SZ][128];
    __shared__ float keys[L_SZ][256];
    __shared__ float q1[256], q2[128], qv[32], qq[256];
    __shared__ float logit[L_SZ];

    for (int idx = t; idx < L_SZ * 64; idx += 256) {
        const int l = idx / 64, c = idx % 64;
        pooled[l][c] = g_pool[(b * L_SZ + l) * 64 + c];
    }
    __syncthreads();

    for (int idx = t; idx < L_SZ * 256; idx += 256) {
        const int l = idx / 256, o = idx % 256;
        float s = kf1b[o];
        for (int i = 0; i < 64; i++) s = fmaf(pooled[l][i], kf1w[o * 64 + i], s);
        h1[l][o] = fmaxf(s, 0.0f);
    }
    __syncthreads();
    for (int idx = t; idx < L_SZ * 128; idx += 256) {
        const int l = idx / 128, o = idx % 128;
        float s = kf2b[o];
        for (int i = 0; i < 256; i++) s = fmaf(h1[l][i], kf2w[o * 256 + i], s);
        h2[l][o] = fmaxf(s, 0.0f);
    }
    __syncthreads();
    for (int idx = t; idx < L_SZ * 256; idx += 256) {
        const int l = idx / 256, o = idx % 256;
        float s = kf3b[o];
        for (int i = 0; i < 128; i++) s = fmaf(h2[l][i], kf3w[o * 128 + i], s);
        keys[l][o] = s;
    }
    __syncthreads();

    {
        float s = qf1b[t];
        for (int i = 0; i < 64; i++) s = fmaf(pooled[0][i], qf1w[t * 64 + i], s);
        q1[t] = fmaxf(s, 0.0f);
    }
    __syncthreads();
    if (t < 128) {
        float s = qf2b[t];
        for (int i = 0; i < 256; i++) s = fmaf(q1[i], qf2w[t * 256 + i], s);
        q2[t] = fmaxf(s, 0.0f);
    }
    __syncthreads();
    if (t < 32) {
        float s = qf3b[t];
        for (int i = 0; i < 128; i++) s = fmaf(q2[i], qf3w[t * 128 + i], s);
        qv[t] = s;
    }
    __syncthreads();
    {
        float s = ab[t];
        for (int i = 0; i < 32; i++) s = fmaf(qv[i], aw[t * 32 + i], s);
        qq[t] = s;
    }
    __syncthreads();
    if (t < L_SZ) {
        float s = 0.0f;
        for (int i = 0; i < 256; i++) s = fmaf(keys[t][i], qq[i], s);
        logit[t] = s;
    }
    __syncthreads();
    if (t == 0) {
        float m = logit[0];
        for (int l = 1; l < L_SZ; l++) m = fmaxf(m, logit[l]);
        float e[L_SZ], ssum = 0.0f;
        for (int l = 0; l < L_SZ; l++) { e[l] = expf(logit[l] - m); ssum += e[l]; }
        const float inv = 1.0f / ssum;
        for (int l = 0; l < L_SZ; l++) g_attn[b * L_SZ + l] = e[l] * inv;
    }
}

// ---------------- fuse: attention-weighted sum of fp32 neigh ----------------
__global__ void fuse_kernel(float* __restrict__ out)
{
    const size_t i = (size_t)blockIdx.x * blockDim.x + threadIdx.x;
    const size_t per_b = (size_t)CH * HW / 4;
    const int b = (int)(i / per_b);
    const size_t rem = i % per_b;

    float a[L_SZ];
    #pragma unroll
    for (int l = 0; l < L_SZ; l++) a[l] = g_attn[b * L_SZ + l];

    const float4* nv = (const float4*)g_neigh;
    float4 s = make_float4(0.f, 0.f, 0.f, 0.f);
    #pragma unroll
    for (int l = 0; l < L_SZ; l++) {
        const float4 v = nv[(size_t)(b * L_SZ + l) * per_b + rem];
        s.x = fmaf(a[l], v.x, s.x);
        s.y = fmaf(a[l], v.y, s.y);
        s.z = fmaf(a[l], v.z, s.z);
        s.w = fmaf(a[l], v.w, s.w);
    }
    ((float4*)out)[i] = s;
}

// ---------------- launch ----------------
extern "C" void kernel_launch(void* const* d_in, const int* in_sizes, int n_in,
                              void* d_out, int out_size)
{
    const float* x    = (const float*)d_in[0];
    const float* nam  = (const float*)d_in[2];
    const float* w1   = (const float*)d_in[3];
    const float* b1   = (const float*)d_in[4];
    const float* w2   = (const float*)d_in[5];
    const float* b2   = (const float*)d_in[6];
    const float* w3   = (const float*)d_in[7];
    const float* b3   = (const float*)d_in[8];
    const float* kf1w = (const float*)d_in[9];
    const float* kf1b = (const float*)d_in[10];
    const float* kf2w = (const float*)d_in[11];
    const float* kf2b = (const float*)d_in[12];
    const float* kf3w = (const float*)d_in[13];
    const float* kf3b = (const float*)d_in[14];
    const float* qf1w = (const float*)d_in[15];
    const float* qf1b = (const float*)d_in[16];
    const float* qf2w = (const float*)d_in[17];
    const float* qf2b = (const float*)d_in[18];
    const float* qf3w = (const float*)d_in[19];
    const float* qf3b = (const float*)d_in[20];
    const float* aw   = (const float*)d_in[21];
    const float* ab   = (const float*)d_in[22];

    float *p_neigh, *p_c3;
    unsigned *p_c1bf, *p_c2bf;
    cudaGetSymbolAddress((void**)&p_neigh, g_neigh);
    cudaGetSymbolAddress((void**)&p_c1bf, g_c1bf);
    cudaGetSymbolAddress((void**)&p_c2bf, g_c2bf);
    cudaGetSymbolAddress((void**)&p_c3, g_c3);

    // double-buffered dynamic smem (bytes): 2*(INR*WP*12 + 16*COUTB*8)*4
    constexpr int SM1 = 2 * (6  * 130 * 12 + 16 * 32 * 8) * 4;   // 107,648
    constexpr int SM2 = 2 * (10 * 66  * 12 + 16 * 32 * 8) * 4;   //  96,128
    constexpr int SM3 = 2 * (18 * 34  * 12 + 16 * 16 * 8) * 4;   //  75,136

    cudaFuncSetAttribute((const void*)conv_bf16<64, 32, 256, 128, 32, true, true>,
                         cudaFuncAttributeMaxDynamicSharedMemorySize, SM1);
    cudaFuncSetAttribute((const void*)conv_bf16<32, 64, 128, 64, 32, false, true>,
                         cudaFuncAttributeMaxDynamicSharedMemorySize, SM2);
    cudaFuncSetAttribute((const void*)conv_bf16<64, 64, 64, 32, 16, false, false>,
                         cudaFuncAttributeMaxDynamicSharedMemorySize, SM3);

    sample_kernel<<<dim3(IMH, NIMG), IMW>>>(x, nam);

    conv_bf16<64, 32, 256, 128, 32, true, true><<<dim3(64, NIMG, 1), 256, SM1>>>(
        p_neigh, w1, b1, nullptr, p_c1bf);
    conv_bf16<32, 64, 128, 64, 32, false, true><<<dim3(16, NIMG, 2), 256, SM2>>>(
        p_c1bf, w2, b2, nullptr, p_c2bf);
    conv_bf16<64, 64, 64, 32, 16, false, false><<<dim3(4, NIMG, 4), 256, SM3>>>(
        p_c2bf, w3, b3, p_c3, nullptr);

    pool_kernel<<<160, 256>>>();
    attn_kernel<<<B_SZ, 256>>>(kf1w, kf1b, kf2w, kf2b, kf3w, kf3b,
                               qf1w, qf1b, qf2w, qf2b, qf3w, qf3b, aw, ab);
    const size_t n4 = (size_t)B_SZ * CH * HW / 4;
    fuse_kernel<<<(unsigned)(n4 / 256), 256>>>((float*)d_out);
}